// round 12
// baseline (speedup 1.0000x reference)
#include <cuda_runtime.h>
#include <cuda_fp16.h>
#include <math.h>
#include <stdint.h>

// Problem constants
#define T_TOK   4096
#define D_MODEL 512
#define D_FF    2048
#define N_EXP   8
#define K_ACT   2
#define NPAIR   (T_TOK * K_ACT)          // 8192
#define BM      128
#define MAX_TILES (NPAIR / BM + N_EXP)   // 72

// ---------------- device scratch ----------------
__device__ int g_pairs[NPAIR];
__device__ int g_tileExpert[MAX_TILES];
__device__ int g_tileRow[MAX_TILES];
__device__ int g_tileRows[MAX_TILES];
__device__ int g_numTiles;

__device__ __align__(16) __half g_Xh [(size_t)T_TOK * D_MODEL];
__device__ __align__(16) __half g_W1h[(size_t)N_EXP * D_MODEL * D_FF]; // [e][k][n] as given
__device__ __align__(16) __half g_W2h[(size_t)N_EXP * D_FF * D_MODEL]; // [e][k][n] as given
__device__ __align__(16) __half g_Ht [(size_t)NPAIR * D_FF];           // gelu(X@W1)

// ---------------- PTX helpers (baseline sm_80+) ----------------
__device__ __forceinline__ uint32_t smem_u32(const void* p) {
    uint32_t a;
    asm("{ .reg .u64 t; cvta.to.shared.u64 t, %1; cvt.u32.u64 %0, t; }" : "=r"(a) : "l"(p));
    return a;
}
#define CP16(dst, src)  asm volatile("cp.async.cg.shared.global [%0], [%1], 16;" :: "r"(dst), "l"(src))
#define CP_COMMIT()     asm volatile("cp.async.commit_group;" ::: "memory")
#define CP_WAIT(n)      asm volatile("cp.async.wait_group %0;" :: "n"(n) : "memory")

__device__ __forceinline__ void ldsm_x4(uint32_t* r, uint32_t addr) {
    asm volatile("ldmatrix.sync.aligned.m8n8.x4.shared.b16 {%0,%1,%2,%3}, [%4];"
        : "=r"(r[0]), "=r"(r[1]), "=r"(r[2]), "=r"(r[3]) : "r"(addr));
}
__device__ __forceinline__ void ldsm_x4_t(uint32_t* r, uint32_t addr) {
    asm volatile("ldmatrix.sync.aligned.m8n8.x4.trans.shared.b16 {%0,%1,%2,%3}, [%4];"
        : "=r"(r[0]), "=r"(r[1]), "=r"(r[2]), "=r"(r[3]) : "r"(addr));
}
__device__ __forceinline__ void mma16816(float* c, const uint32_t* a, uint32_t b0, uint32_t b1) {
    asm volatile("mma.sync.aligned.m16n8k16.row.col.f32.f16.f16.f32 "
        "{%0,%1,%2,%3}, {%4,%5,%6,%7}, {%8,%9}, {%0,%1,%2,%3};"
        : "+f"(c[0]), "+f"(c[1]), "+f"(c[2]), "+f"(c[3])
        : "r"(a[0]), "r"(a[1]), "r"(a[2]), "r"(a[3]), "r"(b0), "r"(b1));
}

// ---------------- fused routing: init+detect+hist+scan+scatter, 1 block ----
__global__ void k_route(const int* __restrict__ sel32, float* __restrict__ out) {
    __shared__ int sh_cnt[N_EXP];
    __shared__ int sh_off[N_EXP];
    int t = threadIdx.x;  // 256
    if (t < N_EXP) sh_cnt[t] = 0;
    __syncthreads();
    int any = 0;
    for (int i = t; i < NPAIR / 2; i += 256) any |= sel32[2 * i + 1];
    int is32 = __syncthreads_or(any);
    for (int p = t; p < NPAIR; p += 256) {
        int e = is32 ? sel32[p] : sel32[2 * p];
        e = min(max(e, 0), N_EXP - 1);
        atomicAdd(&sh_cnt[e], 1);
    }
    __syncthreads();
    if (t == 0) {
        int off = 0, nt = 0;
        for (int e = 0; e < N_EXP; e++) {
            sh_off[e] = off;
            int c = sh_cnt[e];
            out[(size_t)NPAIR * D_MODEL + e] = (float)c / (float)T_TOK;
            for (int r0 = 0; r0 < c; r0 += BM) {
                g_tileExpert[nt] = e; g_tileRow[nt] = off + r0;
                g_tileRows[nt] = min(BM, c - r0); nt++;
            }
            off += c;
        }
        g_numTiles = nt;
    }
    __syncthreads();
    if (t < N_EXP) sh_cnt[t] = 0;  // reuse as fill counters
    __syncthreads();
    for (int p = t; p < NPAIR; p += 256) {
        int e = is32 ? sel32[p] : sel32[2 * p];
        e = min(max(e, 0), N_EXP - 1);
        int pos = sh_off[e] + atomicAdd(&sh_cnt[e], 1);
        g_pairs[pos] = p;  // intra-expert order never changes output bits
    }
}

// ---------------- fused streaming fp32->fp16 convert (X, W1, W2) -----------
#define NXF4  ((size_t)T_TOK * D_MODEL / 4)            // 524288 float4
#define NWF4  ((size_t)N_EXP * D_MODEL * D_FF / 4)     // 2097152 float4
__global__ void k_conv(const float* __restrict__ X,
                       const float* __restrict__ W1,
                       const float* __restrict__ W2) {
    size_t i = (size_t)blockIdx.x * 256 + threadIdx.x;  // float4 index
    const float* src;
    __half* dst;
    size_t o;
    if (i < NXF4)            { src = X;  dst = g_Xh;  o = i; }
    else if (i < NXF4 + NWF4){ src = W1; dst = g_W1h; o = i - NXF4; }
    else                     { src = W2; dst = g_W2h; o = i - NXF4 - NWF4; }
    float4 v = *(const float4*)(src + o * 4);
    __half h[4];
    h[0] = __float2half_rn(v.x); h[1] = __float2half_rn(v.y);
    h[2] = __float2half_rn(v.z); h[3] = __float2half_rn(v.w);
    *(uint2*)(dst + o * 4) = *(uint2*)h;
}

__device__ __forceinline__ float gelu_exact(float v) {
    return 0.5f * v * (1.0f + erff(v * 0.70710678118654752f));
}

// ---------------- 1-term fp16 GEMM via mma.sync ----------------
// CTA tile 128(M) x 256(N), BK=64, 4-stage cp.async, one barrier per chunk.
// 256 threads, 8 warps: 2M x 4N grid, warp tile 64(M) x 64(N).
// A: row-major [M,K] smem (144B rows), non-trans ldsm.
// B: row-major [K,N] smem (64 x 528B rows, direct W layout), trans ldsm.
#define AROWB  144
#define BROWB  528
#define ARR_A  (128 * AROWB)           // 18432 B
#define ARR_B  (64 * BROWB)            // 33792 B
#define STG    (ARR_A + ARR_B)         // 52224 B
#define NSTG   4
#define SMEM_GEMM (NSTG * STG)         // 208896 B

template<bool G1>
__global__ __launch_bounds__(256, 1) void k_mma(float* __restrict__ out) {
    constexpr int KDIM  = G1 ? D_MODEL : D_FF;
    constexpr int NFULL = G1 ? D_FF : D_MODEL;   // B row length (halves)
    constexpr int NCH   = KDIM / 64;             // 8 / 32

    int tile = blockIdx.x;
    if (tile >= g_numTiles) return;
    int e    = g_tileExpert[tile];
    int row0 = g_tileRow[tile];
    int rows = g_tileRows[tile];
    int n0   = blockIdx.y * 256;

    extern __shared__ __align__(128) char smem[];
    uint32_t sb = smem_u32(smem);
    __shared__ int s_rows[128];
    __shared__ int s_pair[128];

    int tid = threadIdx.x;
    int wid = tid >> 5, l = tid & 31;

    if (tid < 128) {
        int rr = min(tid, rows - 1);
        int p = g_pairs[row0 + rr];
        s_pair[tid] = p;
        s_rows[tid] = G1 ? (p >> 1) : (row0 + rr);
    }
    __syncthreads();

    const __half* Bw = (G1 ? g_W1h : g_W2h) + (size_t)e * D_MODEL * D_FF;
    const __half* Asrc = G1 ? g_Xh : g_Ht;

    // A slice: 128 rows x 128B; 256 thr -> row = tid>>1, half 64B (4 CP16)
    int ar = tid >> 1, aq = tid & 1;
    const __half* aP = Asrc + (size_t)s_rows[ar] * KDIM + aq * 32;
    uint32_t dOffA = (uint32_t)ar * AROWB + (uint32_t)aq * 64;
    // B slice: 64 rows x 512B; row = tid>>2, quarter 128B (8 CP16)
    int brw = tid >> 2, bsg = tid & 3;
    const __half* bWp = Bw + (size_t)brw * NFULL + n0 + bsg * 64;
    uint32_t dOffB = (uint32_t)ARR_A + (uint32_t)brw * BROWB + (uint32_t)bsg * 128;

#define LOAD_STAGE(sidx, k0)                                               \
    {                                                                      \
        uint32_t _s = sb + (uint32_t)(sidx) * STG;                         \
        _Pragma("unroll")                                                  \
        for (int i = 0; i < 4; i++)                                        \
            CP16(_s + dOffA + i * 16, aP + (k0) + i * 8);                  \
        _Pragma("unroll")                                                  \
        for (int i = 0; i < 8; i++)                                        \
            CP16(_s + dOffB + i * 16, bWp + (size_t)(k0) * NFULL + i * 8); \
        CP_COMMIT();                                                       \
    }

    int warp_m = (wid >> 2) * 64;     // 0,64
    int warp_n = (wid & 3) * 64;      // 0,64,128,192

    float acc[4][8][4];
#pragma unroll
    for (int i = 0; i < 4; i++)
#pragma unroll
        for (int j = 0; j < 8; j++)
#pragma unroll
            for (int q = 0; q < 4; q++) acc[i][j][q] = 0.0f;

    uint32_t aLane = (uint32_t)((warp_m + (l & 15)) * AROWB + (l >> 4) * 16);
    uint32_t bLane = (uint32_t)ARR_A + (uint32_t)((l & 15) * BROWB + warp_n * 2 + (l >> 4) * 16);

    LOAD_STAGE(0, 0);
    LOAD_STAGE(1, 64);
    LOAD_STAGE(2, 128);

    for (int c = 0; c < NCH; c++) {
        if (c + 2 < NCH)      CP_WAIT(2);
        else if (c + 1 < NCH) CP_WAIT(1);
        else                  CP_WAIT(0);
        __syncthreads();  // stage c ready; all warps done reading stage (c-1)&3
        if (c + 3 < NCH) LOAD_STAGE((c + 3) & 3, (c + 3) * 64);
        uint32_t st = sb + (uint32_t)(c & 3) * STG;
#pragma unroll
        for (int kk = 0; kk < 4; kk++) {
            uint32_t ah[4][4], bw[4][4];
#pragma unroll
            for (int mb = 0; mb < 4; mb++)
                ldsm_x4(ah[mb], st + aLane + (uint32_t)(mb * 16 * AROWB + kk * 32));
#pragma unroll
            for (int nb2 = 0; nb2 < 4; nb2++)
                ldsm_x4_t(bw[nb2], st + bLane + (uint32_t)(kk * 16 * BROWB + nb2 * 32));
#pragma unroll
            for (int mb = 0; mb < 4; mb++)
#pragma unroll
                for (int nb = 0; nb < 8; nb++) {
                    int nb2 = nb >> 1, lo = (nb & 1) * 2;
                    mma16816(acc[mb][nb], ah[mb], bw[nb2][lo], bw[nb2][lo + 1]);
                }
        }
    }

    // epilogue: warp covers 64(M) x 64(N)
#pragma unroll
    for (int mb = 0; mb < 4; mb++)
#pragma unroll
        for (int nb = 0; nb < 8; nb++) {
            int rbase = warp_m + mb * 16 + (l >> 2);
            int col   = warp_n + nb * 8 + (l & 3) * 2;
#pragma unroll
            for (int p = 0; p < 2; p++) {
                int m = rbase + p * 8;
                if (m < rows) {
                    float y0 = acc[mb][nb][2 * p];
                    float y1 = acc[mb][nb][2 * p + 1];
                    if (G1) {
                        __half2 hh;
                        hh.x = __float2half_rn(gelu_exact(y0));
                        hh.y = __float2half_rn(gelu_exact(y1));
                        size_t o = (size_t)(row0 + m) * D_FF + n0 + col;
                        *(uint32_t*)(g_Ht + o) = *(uint32_t*)&hh;
                    } else {
                        size_t o = (size_t)s_pair[m] * D_MODEL + n0 + col;
                        float2 v; v.x = y0; v.y = y1;
                        *(float2*)(out + o) = v;
                    }
                }
            }
        }
#undef LOAD_STAGE
}

// ---------------- launch ----------------
extern "C" void kernel_launch(void* const* d_in, const int* in_sizes, int n_in,
                              void* d_out, int out_size) {
    const float* X     = (const float*)d_in[0];
    const int*   sel32 = (const int*)d_in[1];
    const float* W1    = (const float*)d_in[3];
    const float* W2    = (const float*)d_in[4];
    float*       out   = (float*)d_out;

    cudaFuncSetAttribute((const void*)k_mma<true>,  cudaFuncAttributeMaxDynamicSharedMemorySize, SMEM_GEMM);
    cudaFuncSetAttribute((const void*)k_mma<false>, cudaFuncAttributeMaxDynamicSharedMemorySize, SMEM_GEMM);

    k_route<<<1, 256>>>(sel32, out);
    k_conv<<<(unsigned)((NXF4 + 2 * NWF4) / 256), 256>>>(X, W1, W2);

    dim3 grid1(MAX_TILES, D_FF / 256);    // 72 x 8 = 576 CTAs
    k_mma<true><<<grid1, 256, SMEM_GEMM>>>(out);
    dim3 grid2(MAX_TILES, D_MODEL / 256); // 72 x 2 = 144 CTAs
    k_mma<false><<<grid2, 256, SMEM_GEMM>>>(out);
}

// round 13
// speedup vs baseline: 1.1504x; 1.1504x over previous
#include <cuda_runtime.h>
#include <cuda_fp16.h>
#include <math.h>
#include <stdint.h>

// Problem constants
#define T_TOK   4096
#define D_MODEL 512
#define D_FF    2048
#define N_EXP   8
#define K_ACT   2
#define NPAIR   (T_TOK * K_ACT)          // 8192
#define BM      128
#define MAX_TILES (NPAIR / BM + N_EXP)   // 72

// ---------------- device scratch ----------------
__device__ int g_pairs[NPAIR];
__device__ int g_tileExpert[MAX_TILES];
__device__ int g_tileRow[MAX_TILES];
__device__ int g_tileRows[MAX_TILES];
__device__ int g_numTiles;

__device__ __align__(16) __half g_Xh [(size_t)T_TOK * D_MODEL];
__device__ __align__(16) __half g_W1h[(size_t)N_EXP * D_MODEL * D_FF]; // [e][k][n] as given
__device__ __align__(16) __half g_W2h[(size_t)N_EXP * D_FF * D_MODEL]; // [e][k][n] as given
__device__ __align__(16) __half g_Ht [(size_t)NPAIR * D_FF];           // gelu(X@W1)

// ---------------- PTX helpers (baseline sm_80+) ----------------
__device__ __forceinline__ uint32_t smem_u32(const void* p) {
    uint32_t a;
    asm("{ .reg .u64 t; cvta.to.shared.u64 t, %1; cvt.u32.u64 %0, t; }" : "=r"(a) : "l"(p));
    return a;
}
#define CP16(dst, src)  asm volatile("cp.async.cg.shared.global [%0], [%1], 16;" :: "r"(dst), "l"(src))
#define CP_COMMIT()     asm volatile("cp.async.commit_group;" ::: "memory")
#define CP_WAIT(n)      asm volatile("cp.async.wait_group %0;" :: "n"(n) : "memory")

__device__ __forceinline__ void ldsm_x4(uint32_t* r, uint32_t addr) {
    asm volatile("ldmatrix.sync.aligned.m8n8.x4.shared.b16 {%0,%1,%2,%3}, [%4];"
        : "=r"(r[0]), "=r"(r[1]), "=r"(r[2]), "=r"(r[3]) : "r"(addr));
}
__device__ __forceinline__ void ldsm_x4_t(uint32_t* r, uint32_t addr) {
    asm volatile("ldmatrix.sync.aligned.m8n8.x4.trans.shared.b16 {%0,%1,%2,%3}, [%4];"
        : "=r"(r[0]), "=r"(r[1]), "=r"(r[2]), "=r"(r[3]) : "r"(addr));
}
__device__ __forceinline__ void mma16816(float* c, const uint32_t* a, uint32_t b0, uint32_t b1) {
    asm volatile("mma.sync.aligned.m16n8k16.row.col.f32.f16.f16.f32 "
        "{%0,%1,%2,%3}, {%4,%5,%6,%7}, {%8,%9}, {%0,%1,%2,%3};"
        : "+f"(c[0]), "+f"(c[1]), "+f"(c[2]), "+f"(c[3])
        : "r"(a[0]), "r"(a[1]), "r"(a[2]), "r"(a[3]), "r"(b0), "r"(b1));
}

// ---------------- fused routing: init+detect+hist+scan+scatter, 1 block ----
__global__ void k_route(const int* __restrict__ sel32, float* __restrict__ out) {
    __shared__ int sh_cnt[N_EXP];
    __shared__ int sh_off[N_EXP];
    int t = threadIdx.x;  // 256
    if (t < N_EXP) sh_cnt[t] = 0;
    __syncthreads();
    int any = 0;
    for (int i = t; i < NPAIR / 2; i += 256) any |= sel32[2 * i + 1];
    int is32 = __syncthreads_or(any);
    for (int p = t; p < NPAIR; p += 256) {
        int e = is32 ? sel32[p] : sel32[2 * p];
        e = min(max(e, 0), N_EXP - 1);
        atomicAdd(&sh_cnt[e], 1);
    }
    __syncthreads();
    if (t == 0) {
        int off = 0, nt = 0;
        for (int e = 0; e < N_EXP; e++) {
            sh_off[e] = off;
            int c = sh_cnt[e];
            out[(size_t)NPAIR * D_MODEL + e] = (float)c / (float)T_TOK;
            for (int r0 = 0; r0 < c; r0 += BM) {
                g_tileExpert[nt] = e; g_tileRow[nt] = off + r0;
                g_tileRows[nt] = min(BM, c - r0); nt++;
            }
            off += c;
        }
        g_numTiles = nt;
    }
    __syncthreads();
    if (t < N_EXP) sh_cnt[t] = 0;  // reuse as fill counters
    __syncthreads();
    for (int p = t; p < NPAIR; p += 256) {
        int e = is32 ? sel32[p] : sel32[2 * p];
        e = min(max(e, 0), N_EXP - 1);
        int pos = sh_off[e] + atomicAdd(&sh_cnt[e], 1);
        g_pairs[pos] = p;  // intra-expert order never changes output bits
    }
}

// ---------------- fused streaming fp32->fp16 convert (X, W1, W2) -----------
#define NXF4  ((size_t)T_TOK * D_MODEL / 4)            // 524288 float4
#define NWF4  ((size_t)N_EXP * D_MODEL * D_FF / 4)     // 2097152 float4
__global__ void k_conv(const float* __restrict__ X,
                       const float* __restrict__ W1,
                       const float* __restrict__ W2) {
    size_t i = (size_t)blockIdx.x * 256 + threadIdx.x;  // float4 index
    const float* src;
    __half* dst;
    size_t o;
    if (i < NXF4)            { src = X;  dst = g_Xh;  o = i; }
    else if (i < NXF4 + NWF4){ src = W1; dst = g_W1h; o = i - NXF4; }
    else                     { src = W2; dst = g_W2h; o = i - NXF4 - NWF4; }
    float4 v = *(const float4*)(src + o * 4);
    __half h[4];
    h[0] = __float2half_rn(v.x); h[1] = __float2half_rn(v.y);
    h[2] = __float2half_rn(v.z); h[3] = __float2half_rn(v.w);
    *(uint2*)(dst + o * 4) = *(uint2*)h;
}

__device__ __forceinline__ float gelu_exact(float v) {
    return 0.5f * v * (1.0f + erff(v * 0.70710678118654752f));
}

// ---------------- 1-term fp16 GEMM via mma.sync ----------------
// CTA tile 128(M) x 256(N), BK=64, 4-stage cp.async, one barrier per chunk.
// 512 threads, 16 warps: 4M x 4N, warp tile 32(M) x 64(N).
// Inner loop software-pipelines fragments: ldsm(kk+1) issued before mma(kk).
#define AROWB  144
#define BROWB  528
#define ARR_A  (128 * AROWB)           // 18432 B
#define ARR_B  (64 * BROWB)            // 33792 B
#define STG    (ARR_A + ARR_B)         // 52224 B
#define NSTG   4
#define SMEM_GEMM (NSTG * STG)         // 208896 B

template<bool G1>
__global__ __launch_bounds__(512, 1) void k_mma(float* __restrict__ out) {
    constexpr int KDIM  = G1 ? D_MODEL : D_FF;
    constexpr int NFULL = G1 ? D_FF : D_MODEL;   // B row length (halves)
    constexpr int NCH   = KDIM / 64;             // 8 / 32

    int tile = blockIdx.x;
    if (tile >= g_numTiles) return;
    int e    = g_tileExpert[tile];
    int row0 = g_tileRow[tile];
    int rows = g_tileRows[tile];
    int n0   = blockIdx.y * 256;

    extern __shared__ __align__(128) char smem[];
    uint32_t sb = smem_u32(smem);
    __shared__ int s_rows[128];
    __shared__ int s_pair[128];

    int tid = threadIdx.x;
    int wid = tid >> 5, l = tid & 31;

    if (tid < 128) {
        int rr = min(tid, rows - 1);
        int p = g_pairs[row0 + rr];
        s_pair[tid] = p;
        s_rows[tid] = G1 ? (p >> 1) : (row0 + rr);
    }
    __syncthreads();

    const __half* Bw = (G1 ? g_W1h : g_W2h) + (size_t)e * D_MODEL * D_FF;
    const __half* Asrc = G1 ? g_Xh : g_Ht;

    // A slice: 128 rows x 128B; row = tid>>2, quarter 32B (2 CP16)
    int ar = tid >> 2, aq = tid & 3;
    const __half* aP = Asrc + (size_t)s_rows[ar] * KDIM + aq * 16;
    uint32_t dOffA = (uint32_t)ar * AROWB + (uint32_t)aq * 32;
    // B slice: 64 rows x 512B; row = tid>>3, eighth 64B (4 CP16)
    int brw = tid >> 3, bsg = tid & 7;
    const __half* bWp = Bw + (size_t)brw * NFULL + n0 + bsg * 32;
    uint32_t dOffB = (uint32_t)ARR_A + (uint32_t)brw * BROWB + (uint32_t)bsg * 64;

#define LOAD_STAGE(sidx, k0)                                             \
    {                                                                    \
        uint32_t _s = sb + (uint32_t)(sidx) * STG;                       \
        _Pragma("unroll")                                                \
        for (int i = 0; i < 2; i++)                                      \
            CP16(_s + dOffA + i * 16, aP + (k0) + i * 8);                \
        _Pragma("unroll")                                                \
        for (int i = 0; i < 4; i++)                                      \
            CP16(_s + dOffB + i * 16, bWp + (size_t)(k0) * NFULL + i * 8); \
        CP_COMMIT();                                                     \
    }

    int warp_m = (wid >> 2) * 32;     // 0,32,64,96
    int warp_n = (wid & 3) * 64;      // 0,64,128,192

    float acc[2][8][4];
#pragma unroll
    for (int i = 0; i < 2; i++)
#pragma unroll
        for (int j = 0; j < 8; j++)
#pragma unroll
            for (int q = 0; q < 4; q++) acc[i][j][q] = 0.0f;

    uint32_t aLane = (uint32_t)((warp_m + (l & 15)) * AROWB + (l >> 4) * 16);
    uint32_t bLane = (uint32_t)ARR_A + (uint32_t)((l & 15) * BROWB + warp_n * 2 + (l >> 4) * 16);

    LOAD_STAGE(0, 0);
    LOAD_STAGE(1, 64);
    LOAD_STAGE(2, 128);

    // double-buffered fragments
    uint32_t ah[2][2][4], bw[2][4][4];

    for (int c = 0; c < NCH; c++) {
        if (c + 2 < NCH)      CP_WAIT(2);
        else if (c + 1 < NCH) CP_WAIT(1);
        else                  CP_WAIT(0);
        __syncthreads();  // stage c ready; all warps done reading stage (c-1)&3
        if (c + 3 < NCH) LOAD_STAGE((c + 3) & 3, (c + 3) * 64);
        uint32_t st = sb + (uint32_t)(c & 3) * STG;

        // preload kk=0 fragments into buffer 0
#pragma unroll
        for (int mb = 0; mb < 2; mb++)
            ldsm_x4(ah[0][mb], st + aLane + (uint32_t)(mb * 16 * AROWB));
#pragma unroll
        for (int nb2 = 0; nb2 < 4; nb2++)
            ldsm_x4_t(bw[0][nb2], st + bLane + (uint32_t)(nb2 * 32));

#pragma unroll
        for (int kk = 0; kk < 4; kk++) {
            int cur = kk & 1, nxt = cur ^ 1;
            if (kk < 3) {  // issue next-kk ldsm BEFORE this kk's MMAs
#pragma unroll
                for (int mb = 0; mb < 2; mb++)
                    ldsm_x4(ah[nxt][mb], st + aLane + (uint32_t)(mb * 16 * AROWB + (kk + 1) * 32));
#pragma unroll
                for (int nb2 = 0; nb2 < 4; nb2++)
                    ldsm_x4_t(bw[nxt][nb2], st + bLane + (uint32_t)((kk + 1) * 16 * BROWB + nb2 * 32));
            }
#pragma unroll
            for (int mb = 0; mb < 2; mb++)
#pragma unroll
                for (int nb = 0; nb < 8; nb++) {
                    int nb2 = nb >> 1, lo = (nb & 1) * 2;
                    mma16816(acc[mb][nb], ah[cur][mb], bw[cur][nb2][lo], bw[cur][nb2][lo + 1]);
                }
        }
    }

    // epilogue
#pragma unroll
    for (int mb = 0; mb < 2; mb++)
#pragma unroll
        for (int nb = 0; nb < 8; nb++) {
            int rbase = warp_m + mb * 16 + (l >> 2);
            int col   = warp_n + nb * 8 + (l & 3) * 2;
#pragma unroll
            for (int p = 0; p < 2; p++) {
                int m = rbase + p * 8;
                if (m < rows) {
                    float y0 = acc[mb][nb][2 * p];
                    float y1 = acc[mb][nb][2 * p + 1];
                    if (G1) {
                        __half2 hh;
                        hh.x = __float2half_rn(gelu_exact(y0));
                        hh.y = __float2half_rn(gelu_exact(y1));
                        size_t o = (size_t)(row0 + m) * D_FF + n0 + col;
                        *(uint32_t*)(g_Ht + o) = *(uint32_t*)&hh;
                    } else {
                        size_t o = (size_t)s_pair[m] * D_MODEL + n0 + col;
                        float2 v; v.x = y0; v.y = y1;
                        *(float2*)(out + o) = v;
                    }
                }
            }
        }
#undef LOAD_STAGE
}

// ---------------- launch ----------------
extern "C" void kernel_launch(void* const* d_in, const int* in_sizes, int n_in,
                              void* d_out, int out_size) {
    const float* X     = (const float*)d_in[0];
    const int*   sel32 = (const int*)d_in[1];
    const float* W1    = (const float*)d_in[3];
    const float* W2    = (const float*)d_in[4];
    float*       out   = (float*)d_out;

    cudaFuncSetAttribute((const void*)k_mma<true>,  cudaFuncAttributeMaxDynamicSharedMemorySize, SMEM_GEMM);
    cudaFuncSetAttribute((const void*)k_mma<false>, cudaFuncAttributeMaxDynamicSharedMemorySize, SMEM_GEMM);

    k_route<<<1, 256>>>(sel32, out);
    k_conv<<<(unsigned)((NXF4 + 2 * NWF4) / 256), 256>>>(X, W1, W2);

    dim3 grid1(MAX_TILES, D_FF / 256);    // 72 x 8 = 576 CTAs
    k_mma<true><<<grid1, 512, SMEM_GEMM>>>(out);
    dim3 grid2(MAX_TILES, D_MODEL / 256); // 72 x 2 = 144 CTAs
    k_mma<false><<<grid2, 512, SMEM_GEMM>>>(out);
}